// round 1
// baseline (speedup 1.0000x reference)
#include <cuda_runtime.h>

// Spatial GCN (grid-graph) + per-(c,l) weight + BatchNorm2d(train) + LeakyReLU(0.2)
//
// Structure exploited: adj = D^-1 A + I for a 24x24 4-neighbor grid =>
//   support[l] = x[l]*adj[l,l] + sum_{k in {l+-1, l+-24} valid} x[k]*adj[k,l]
// i.e. a 5-point stencil (<=5 nonzeros per adj column). Coefficients are read
// from the adj input, so the kernel stays faithful to the provided matrix.
//
// Fusion: one CTA per channel. The channel's full (B=64, N=576) plane set is
// 147456 B and fits in opt-in shared memory, so everything (stencil, weight,
// batch statistics, normalize, leaky relu) happens in a single HBM pass.

#define GRID_N   24
#define N_NODES  576           // 24*24
#define BATCH    64
#define CH       16            // batch chunk for in-place y overwrite
#define NCHUNK   (BATCH / CH)
#define NELEM    (BATCH * N_NODES)   // 36864 per channel
#define NF4      (NELEM / 4)         // 9216 float4
#define PLANE_F4 (N_NODES / 4)       // 144 float4 per (b,c) plane
#define BN_EPS   1e-4f
#define SLOPE    0.2f

__global__ __launch_bounds__(N_NODES, 1)
void gcn_bn_lrelu_kernel(const float* __restrict__ x,
                         const float* __restrict__ adj,
                         const float* __restrict__ weight,
                         const float* __restrict__ gamma,
                         const float* __restrict__ beta,
                         float* __restrict__ out,
                         int C)
{
    extern __shared__ float buf[];          // [BATCH * N_NODES] x, later y
    __shared__ float red[64];
    __shared__ float s_scale, s_bias;

    const int c = blockIdx.x;
    const int t = threadIdx.x;              // 0..575, = node id l
    const int l = t;
    const int i = l / GRID_N;
    const int j = l - i * GRID_N;

    // ---- per-node stencil coefficients from adj column l ----
    const float cC = adj[(size_t)l * N_NODES + l];
    float cL = 0.f, cR = 0.f, cU = 0.f, cD = 0.f;
    int lL = l, lR = l, lU = l, lD = l;     // clamped neighbor indices
    if (j > 0)          { lL = l - 1;      cL = adj[(size_t)lL * N_NODES + l]; }
    if (j < GRID_N - 1) { lR = l + 1;      cR = adj[(size_t)lR * N_NODES + l]; }
    if (i > 0)          { lU = l - GRID_N; cU = adj[(size_t)lU * N_NODES + l]; }
    if (i < GRID_N - 1) { lD = l + GRID_N; cD = adj[(size_t)lD * N_NODES + l]; }
    const float w = weight[(size_t)c * N_NODES + l];

    // ---- Phase 1: stream all 64 batch planes of channel c into smem ----
    // x element index for (b, c, node e): (b*C + c)*576 + e  -> float4 form
    const float4* __restrict__ x4 = (const float4*)x;
    float4* buf4 = (float4*)buf;
#pragma unroll
    for (int k = 0; k < NF4 / N_NODES; ++k) {      // 16 iterations
        int f = t + k * N_NODES;                   // 0..9215
        int b = f / PLANE_F4;
        int q = f - b * PLANE_F4;
        buf4[f] = x4[(size_t)(b * C + c) * PLANE_F4 + q];
    }
    __syncthreads();

    // ---- Phase 2: stencil * weight, overwrite x with y in smem, accumulate stats ----
    float sum = 0.f, sumsq = 0.f;
#pragma unroll
    for (int ch = 0; ch < NCHUNK; ++ch) {
        float yv[CH];
#pragma unroll
        for (int k = 0; k < CH; ++k) {
            const float* xb = buf + (ch * CH + k) * N_NODES;
            float s = cC * xb[l];
            s = fmaf(cL, xb[lL], s);
            s = fmaf(cR, xb[lR], s);
            s = fmaf(cU, xb[lU], s);
            s = fmaf(cD, xb[lD], s);
            float y = s * w;
            yv[k] = y;
            sum += y;
            sumsq = fmaf(y, y, sumsq);
        }
        __syncthreads();   // all reads of this chunk's x done before overwrite
#pragma unroll
        for (int k = 0; k < CH; ++k)
            buf[(ch * CH + k) * N_NODES + l] = yv[k];
        // next chunk reads disjoint slots; no barrier needed here
    }
    __syncthreads();       // y stores visible before phase 3

    // ---- block reduction for mean / var ----
#pragma unroll
    for (int off = 16; off > 0; off >>= 1) {
        sum   += __shfl_down_sync(0xffffffffu, sum,   off);
        sumsq += __shfl_down_sync(0xffffffffu, sumsq, off);
    }
    const int warp = t >> 5, lane = t & 31;        // 18 warps
    if (lane == 0) { red[warp] = sum; red[32 + warp] = sumsq; }
    __syncthreads();
    if (t == 0) {
        float s = 0.f, q = 0.f;
#pragma unroll
        for (int wi = 0; wi < N_NODES / 32; ++wi) { s += red[wi]; q += red[32 + wi]; }
        const float inv_n = 1.f / (float)NELEM;
        float mean = s * inv_n;
        float var  = fmaf(q, inv_n, -mean * mean);
        float rstd = rsqrtf(var + BN_EPS);
        float g  = gamma[c];
        float sc = g * rstd;
        s_scale = sc;
        s_bias  = fmaf(-mean, sc, beta[c]);
    }
    __syncthreads();
    const float sc = s_scale, bi = s_bias;

    // ---- Phase 3: normalize + LeakyReLU, stream out ----
    float4* __restrict__ out4 = (float4*)out;
#pragma unroll
    for (int k = 0; k < NF4 / N_NODES; ++k) {
        int f = t + k * N_NODES;
        int b = f / PLANE_F4;
        int q = f - b * PLANE_F4;
        float4 v = buf4[f];
        v.x = fmaf(v.x, sc, bi);
        v.y = fmaf(v.y, sc, bi);
        v.z = fmaf(v.z, sc, bi);
        v.w = fmaf(v.w, sc, bi);
        v.x = (v.x >= 0.f) ? v.x : SLOPE * v.x;
        v.y = (v.y >= 0.f) ? v.y : SLOPE * v.y;
        v.z = (v.z >= 0.f) ? v.z : SLOPE * v.z;
        v.w = (v.w >= 0.f) ? v.w : SLOPE * v.w;
        out4[(size_t)(b * C + c) * PLANE_F4 + q] = v;
    }
}

extern "C" void kernel_launch(void* const* d_in, const int* in_sizes, int n_in,
                              void* d_out, int out_size)
{
    const float* x      = (const float*)d_in[0];
    const float* adj    = (const float*)d_in[1];
    const float* weight = (const float*)d_in[2];
    const float* gamma  = (const float*)d_in[3];
    const float* beta   = (const float*)d_in[4];
    float* out = (float*)d_out;

    const int C = in_sizes[2] / N_NODES;   // 512
    const size_t smem = (size_t)NELEM * sizeof(float);  // 147456 B

    cudaFuncSetAttribute(gcn_bn_lrelu_kernel,
                         cudaFuncAttributeMaxDynamicSharedMemorySize, (int)smem);
    gcn_bn_lrelu_kernel<<<C, N_NODES, smem>>>(x, adj, weight, gamma, beta, out, C);
}

// round 2
// speedup vs baseline: 1.1602x; 1.1602x over previous
#include <cuda_runtime.h>
#include <cuda_pipeline_primitives.h>

// Spatial GCN (24x24 grid) + weight + BatchNorm2d(train) + LeakyReLU(0.2)
//
// adj = D^-1 A + I on a 4-neighbor grid => support[.,l] is a 5-point stencil
// with coefficients read from adj column l.
//
// R2 structure: one CTA per channel, 576 threads (thread = node l).
//  - x streamed in 4-plane chunks via cp.async into a 4-stage smem ring (36KB)
//  - y kept entirely in registers (64 floats/thread) -> no y smem round-trips
//  - batch statistics accumulated inline, block-reduced once
//  - normalize + LeakyReLU + store straight from registers (coalesced STG.32)
// This overlaps the DRAM read stream with the smem-bound stencil compute.

#define GRID_N   24
#define NN       576            // nodes
#define BATCH    64
#define PPC      4              // planes per chunk
#define NCHUNK   (BATCH / PPC)  // 16
#define NSTAGE   4              // pipeline depth
#define STAGE_F4 (PPC * NN / 4) // 576 float4 per stage
#define BN_EPS   1e-4f
#define SLOPE    0.2f

__global__ __launch_bounds__(NN, 1)
void gcn_bn_lrelu_kernel(const float* __restrict__ x,
                         const float* __restrict__ adj,
                         const float* __restrict__ weight,
                         const float* __restrict__ gamma,
                         const float* __restrict__ beta,
                         float* __restrict__ out,
                         int C)
{
    __shared__ float buf[NSTAGE * PPC * NN];   // 36864 B ring buffer
    __shared__ float red[64];
    __shared__ float s_sb[2];                  // scale, bias

    const int c = blockIdx.x;
    const int t = threadIdx.x;                 // node id l
    const int l = t;
    const int i = l / GRID_N;
    const int j = l - i * GRID_N;

    // ---- stencil coefficients from adj column l ----
    const float cC = adj[(size_t)l * NN + l];
    float cL = 0.f, cR = 0.f, cU = 0.f, cD = 0.f;
    int lL = l, lR = l, lU = l, lD = l;
    if (j > 0)          { lL = l - 1;      cL = adj[(size_t)lL * NN + l]; }
    if (j < GRID_N - 1) { lR = l + 1;      cR = adj[(size_t)lR * NN + l]; }
    if (i > 0)          { lU = l - GRID_N; cU = adj[(size_t)lU * NN + l]; }
    if (i < GRID_N - 1) { lD = l + GRID_N; cD = adj[(size_t)lD * NN + l]; }
    const float w = weight[(size_t)c * NN + l];

    // ---- cp.async load mapping: chunk ch = planes [4ch, 4ch+4) ----
    // thread t fetches one float4: plane offset b_off = t/144, quad q = t%144
    const int b_off = t / (NN / 4);            // 0..3
    const int q     = t - b_off * (NN / 4);    // 0..143
    const float4* __restrict__ x4 = (const float4*)x;
    float4* buf4 = (float4*)buf;

    // prologue: fill the ring
#pragma unroll
    for (int s = 0; s < NSTAGE; ++s) {
        const float4* src = x4 + ((size_t)((s * PPC + b_off) * C + c)) * (NN / 4) + q;
        __pipeline_memcpy_async(&buf4[s * STAGE_F4 + t], src, 16);
        __pipeline_commit();
    }

    float y[BATCH];
    float sum = 0.f, sq = 0.f;

#pragma unroll
    for (int ch = 0; ch < NCHUNK; ++ch) {
        __pipeline_wait_prior(NSTAGE - 1);     // chunk ch's group complete
        __syncthreads();
        const int st = ch & (NSTAGE - 1);
        const float* base = buf + st * PPC * NN;
#pragma unroll
        for (int k = 0; k < PPC; ++k) {
            const float* xb = base + k * NN;
            float s0 = cC * xb[l];
            s0 = fmaf(cL, xb[lL], s0);
            s0 = fmaf(cR, xb[lR], s0);
            s0 = fmaf(cU, xb[lU], s0);
            s0 = fmaf(cD, xb[lD], s0);
            float yy = s0 * w;
            y[ch * PPC + k] = yy;
            sum += yy;
            sq = fmaf(yy, yy, sq);
        }
        __syncthreads();                       // all reads of stage done
        const int nc = ch + NSTAGE;
        if (nc < NCHUNK) {
            const float4* src = x4 + ((size_t)((nc * PPC + b_off) * C + c)) * (NN / 4) + q;
            __pipeline_memcpy_async(&buf4[st * STAGE_F4 + t], src, 16);
        }
        __pipeline_commit();                   // keep group accounting uniform
    }

    // ---- block reduction: mean / var ----
#pragma unroll
    for (int off = 16; off > 0; off >>= 1) {
        sum += __shfl_down_sync(0xffffffffu, sum, off);
        sq  += __shfl_down_sync(0xffffffffu, sq,  off);
    }
    const int warp = t >> 5, lane = t & 31;    // 18 warps
    if (lane == 0) { red[warp] = sum; red[32 + warp] = sq; }
    __syncthreads();
    if (t == 0) {
        float s = 0.f, qq = 0.f;
#pragma unroll
        for (int wi = 0; wi < NN / 32; ++wi) { s += red[wi]; qq += red[32 + wi]; }
        const float inv_n = 1.f / (float)(BATCH * NN);
        float mean = s * inv_n;
        float var  = fmaf(qq, inv_n, -mean * mean);
        float rstd = rsqrtf(var + BN_EPS);
        float sc   = gamma[c] * rstd;
        s_sb[0] = sc;
        s_sb[1] = fmaf(-mean, sc, beta[c]);
    }
    __syncthreads();
    const float sc = s_sb[0], bi = s_sb[1];

    // ---- normalize + LeakyReLU + store (coalesced per-warp 128B rows) ----
#pragma unroll
    for (int b = 0; b < BATCH; ++b) {
        float v = fmaf(y[b], sc, bi);
        v = (v >= 0.f) ? v : SLOPE * v;
        out[(size_t)(b * C + c) * NN + l] = v;
    }
}

extern "C" void kernel_launch(void* const* d_in, const int* in_sizes, int n_in,
                              void* d_out, int out_size)
{
    const float* x      = (const float*)d_in[0];
    const float* adj    = (const float*)d_in[1];
    const float* weight = (const float*)d_in[2];
    const float* gamma  = (const float*)d_in[3];
    const float* beta   = (const float*)d_in[4];
    float* out = (float*)d_out;

    const int C = in_sizes[2] / NN;            // 512
    gcn_bn_lrelu_kernel<<<C, NN>>>(x, adj, weight, gamma, beta, out, C);
}